// round 1
// baseline (speedup 1.0000x reference)
#include <cuda_runtime.h>

// Problem constants
#define B_    8
#define N_    4096
#define DN_   64
#define E_    1048576
#define H_    128
#define DM_   64
#define F_    64
#define ROWS_ (B_ * N_)          // 32768

// Shared memory layout (floats)
//   XsT  [128][128]  transposed input tile (reused as HsT after GEMM1)
//   W1s  [128][128]
//   W2s  [128][64]
//   sb1  [128], sb2[64], sVal[128], sSeg[128], sSOff[128], sTOff[128]
#define SMEM_FLOATS 41664
#define SMEM_BYTES  (SMEM_FLOATS * 4)

// Scatter scratch (device globals: no allocation allowed)
__device__ float g_sums[ROWS_ * DM_];   // 8 MB
__device__ float g_cnts[ROWS_];         // 128 KB

// ---------------- packed f32x2 helpers (Blackwell FFMA2) ----------------
static __device__ __forceinline__ unsigned long long pack2(float x) {
    unsigned long long r;
    asm("mov.b64 %0, {%1, %1};" : "=l"(r) : "f"(x));
    return r;
}
static __device__ __forceinline__ void fma2(unsigned long long& d,
                                            unsigned long long a,
                                            unsigned long long b) {
    asm("fma.rn.f32x2 %0, %1, %2, %0;" : "+l"(d) : "l"(a), "l"(b));
}
static __device__ __forceinline__ void unpack2(unsigned long long v, float& a, float& b) {
    asm("mov.b64 {%0, %1}, %2;" : "=f"(a), "=f"(b) : "l"(v));
}
static __device__ __forceinline__ void red4(float* p, float a, float b, float c, float d) {
    asm volatile("red.global.add.v4.f32 [%0], {%1, %2, %3, %4};"
                 :: "l"(p), "f"(a), "f"(b), "f"(c), "f"(d) : "memory");
}

// ---------------- zero scratch ----------------
__global__ void zero_scratch() {
    unsigned i = blockIdx.x * 256u + threadIdx.x;
    float4 z = make_float4(0.f, 0.f, 0.f, 0.f);
    const unsigned n_sum4 = (ROWS_ * DM_) / 4;   // 524288
    if (i < n_sum4)
        reinterpret_cast<float4*>(g_sums)[i] = z;
    else
        reinterpret_cast<float4*>(g_cnts)[i - n_sum4] = z;
}

// ---------------- edge message kernel ----------------
// One block = 128 edges. 256 threads; tx = tid&15 (edge octet), ty = tid>>4 (col group).
__global__ void __launch_bounds__(256, 1)
edge_msg_kernel(const float* __restrict__ nf,
                const int*   __restrict__ eb, const int* __restrict__ es,
                const int*   __restrict__ ed, const float* __restrict__ ev,
                const float* __restrict__ W1, const float* __restrict__ b1,
                const float* __restrict__ W2, const float* __restrict__ b2)
{
    extern __shared__ float sm[];
    float* XsT  = sm;                 // [k][edge], 128x128
    float* W1s  = sm + 16384;         // [k][h],    128x128
    float* W2s  = sm + 32768;         // [k][d],    128x64
    float* sb1  = sm + 40960;
    float* sb2  = sm + 41088;
    float* sVal = sm + 41152;
    int*   sSeg  = (int*)(sm + 41280);
    int*   sSOff = (int*)(sm + 41408);
    int*   sTOff = (int*)(sm + 41536);

    const int tid = threadIdx.x;
    const int e0  = blockIdx.x << 7;

    if (tid < 128) {
        int e   = e0 + tid;
        int b   = eb[e];
        int seg = b * N_ + es[e];
        sSeg[tid]  = seg;
        sSOff[tid] = seg * DN_;
        sTOff[tid] = (b * N_ + ed[e]) * DN_;
        sVal[tid]  = ev[e];
        sb1[tid]   = b1[tid];
        if (tid < 64) sb2[tid] = b2[tid];
    }
    __syncthreads();

    // one count per edge
    if (tid < 128) atomicAdd(&g_cnts[sSeg[tid]], 1.0f);

    // stage weights (L2-hot across all 8192 blocks)
    {
        const float4* s1 = (const float4*)W1;
        float4*       d1 = (float4*)W1s;
        #pragma unroll 4
        for (int i = tid; i < 4096; i += 256) d1[i] = s1[i];
        const float4* s2 = (const float4*)W2;
        float4*       d2 = (float4*)W2s;
        #pragma unroll 2
        for (int i = tid; i < 2048; i += 256) d2[i] = s2[i];
    }

    // gather X transposed: XsT[k][edge]. Warp lanes cover consecutive edges
    // at a fixed feature chunk -> conflict-free smem stores.
    {
        int lane = tid & 127;
        int soff = sSOff[lane], toff = sTOff[lane];
        #pragma unroll
        for (int p = (tid >> 7); p < 32; p += 2) {
            float4 v = (p < 16) ? *(const float4*)(nf + soff + p * 4)
                                : *(const float4*)(nf + toff + (p - 16) * 4);
            int k = p * 4;
            XsT[(k + 0) * 128 + lane] = v.x;
            XsT[(k + 1) * 128 + lane] = v.y;
            XsT[(k + 2) * 128 + lane] = v.z;
            XsT[(k + 3) * 128 + lane] = v.w;
        }
    }
    __syncthreads();

    const int tx = tid & 15, ty = tid >> 4;

    // ---- GEMM1: H[128e x 128h] = X @ W1 (f32x2 packed accumulators) ----
    unsigned long long acc[8][4];
    #pragma unroll
    for (int i = 0; i < 8; i++)
        #pragma unroll
        for (int jp = 0; jp < 4; jp++) acc[i][jp] = 0ull;

    const float* Xa = XsT + tx * 8;
    const float* Wb = W1s + ty * 8;
    #pragma unroll 4
    for (int kk = 0; kk < 128; kk++) {
        float4 a0 = *(const float4*)(Xa + kk * 128);
        float4 a1 = *(const float4*)(Xa + kk * 128 + 4);
        ulonglong2 bq0 = *(const ulonglong2*)(Wb + kk * 128);
        ulonglong2 bq1 = *(const ulonglong2*)(Wb + kk * 128 + 4);
        float av[8] = {a0.x, a0.y, a0.z, a0.w, a1.x, a1.y, a1.z, a1.w};
        #pragma unroll
        for (int i = 0; i < 8; i++) {
            unsigned long long ap = pack2(av[i]);
            fma2(acc[i][0], ap, bq0.x);
            fma2(acc[i][1], ap, bq0.y);
            fma2(acc[i][2], ap, bq1.x);
            fma2(acc[i][3], ap, bq1.y);
        }
    }

    // bias + relu
    float hv[8][8];
    #pragma unroll
    for (int i = 0; i < 8; i++)
        #pragma unroll
        for (int jp = 0; jp < 4; jp++)
            unpack2(acc[i][jp], hv[i][2 * jp], hv[i][2 * jp + 1]);
    #pragma unroll
    for (int j = 0; j < 8; j++) {
        float bb = sb1[ty * 8 + j];
        #pragma unroll
        for (int i = 0; i < 8; i++) hv[i][j] = fmaxf(hv[i][j] + bb, 0.f);
    }

    __syncthreads();              // all XsT reads complete
    float* HsT = XsT;             // reuse: HsT[h][edge]
    #pragma unroll
    for (int j = 0; j < 8; j++) {
        float4 v0 = make_float4(hv[0][j], hv[1][j], hv[2][j], hv[3][j]);
        float4 v1 = make_float4(hv[4][j], hv[5][j], hv[6][j], hv[7][j]);
        *(float4*)&HsT[(ty * 8 + j) * 128 + tx * 8]     = v0;
        *(float4*)&HsT[(ty * 8 + j) * 128 + tx * 8 + 4] = v1;
    }
    __syncthreads();

    // ---- GEMM2: M[128e x 64d] = H @ W2, then weight + scatter ----
    unsigned long long a2[8][2];
    #pragma unroll
    for (int i = 0; i < 8; i++) { a2[i][0] = 0ull; a2[i][1] = 0ull; }

    const float* Ha  = HsT + tx * 8;
    const float* Wb2 = W2s + ty * 4;
    #pragma unroll 4
    for (int kk = 0; kk < 128; kk++) {
        const float* hk = Ha + kk * 128;
        float4 a0 = *(const float4*)hk;
        float4 a1 = *(const float4*)(hk + 4);
        ulonglong2 bq = *(const ulonglong2*)(Wb2 + kk * 64);
        float av[8] = {a0.x, a0.y, a0.z, a0.w, a1.x, a1.y, a1.z, a1.w};
        #pragma unroll
        for (int i = 0; i < 8; i++) {
            unsigned long long ap = pack2(av[i]);
            fma2(a2[i][0], ap, bq.x);
            fma2(a2[i][1], ap, bq.y);
        }
    }

    float4 bb2 = *(const float4*)(sb2 + ty * 4);
    #pragma unroll
    for (int i = 0; i < 8; i++) {
        float m0, m1, m2, m3;
        unpack2(a2[i][0], m0, m1);
        unpack2(a2[i][1], m2, m3);
        int   e = tx * 8 + i;
        float v = sVal[e];
        m0 = (m0 + bb2.x) * v;
        m1 = (m1 + bb2.y) * v;
        m2 = (m2 + bb2.z) * v;
        m3 = (m3 + bb2.w) * v;
        float* p = g_sums + (long)sSeg[e] * DM_ + ty * 4;
        red4(p, m0, m1, m2, m3);
    }
}

// ---------------- node update kernel ----------------
__global__ void __launch_bounds__(256, 1)
node_upd_kernel(const float* __restrict__ nf,
                const float* __restrict__ W1, const float* __restrict__ b1,
                const float* __restrict__ W2, const float* __restrict__ b2,
                float* __restrict__ out)
{
    extern __shared__ float sm[];
    float* XsT = sm;
    float* W1s = sm + 16384;
    float* W2s = sm + 32768;
    float* sb1 = sm + 40960;
    float* sb2 = sm + 41088;

    const int tid = threadIdx.x;
    const int r0  = blockIdx.x << 7;

    if (tid < 128) {
        sb1[tid] = b1[tid];
        if (tid < 64) sb2[tid] = b2[tid];
    }
    {
        const float4* s1 = (const float4*)W1;
        float4*       d1 = (float4*)W1s;
        #pragma unroll 4
        for (int i = tid; i < 4096; i += 256) d1[i] = s1[i];
        const float4* s2 = (const float4*)W2;
        float4*       d2 = (float4*)W2s;
        #pragma unroll 2
        for (int i = tid; i < 2048; i += 256) d2[i] = s2[i];
    }
    {
        int lane = tid & 127;
        int r = r0 + lane;
        float inv = 1.0f / fmaxf(g_cnts[r], 1.0f);
        #pragma unroll
        for (int p = (tid >> 7); p < 32; p += 2) {
            float4 v;
            if (p < 16) {
                v = *(const float4*)(nf + (long)r * DN_ + p * 4);
            } else {
                v = *(const float4*)(g_sums + (long)r * DM_ + (p - 16) * 4);
                v.x *= inv; v.y *= inv; v.z *= inv; v.w *= inv;
            }
            int k = p * 4;
            XsT[(k + 0) * 128 + lane] = v.x;
            XsT[(k + 1) * 128 + lane] = v.y;
            XsT[(k + 2) * 128 + lane] = v.z;
            XsT[(k + 3) * 128 + lane] = v.w;
        }
    }
    __syncthreads();

    const int tx = tid & 15, ty = tid >> 4;

    unsigned long long acc[8][4];
    #pragma unroll
    for (int i = 0; i < 8; i++)
        #pragma unroll
        for (int jp = 0; jp < 4; jp++) acc[i][jp] = 0ull;

    const float* Xa = XsT + tx * 8;
    const float* Wb = W1s + ty * 8;
    #pragma unroll 4
    for (int kk = 0; kk < 128; kk++) {
        float4 a0 = *(const float4*)(Xa + kk * 128);
        float4 a1 = *(const float4*)(Xa + kk * 128 + 4);
        ulonglong2 bq0 = *(const ulonglong2*)(Wb + kk * 128);
        ulonglong2 bq1 = *(const ulonglong2*)(Wb + kk * 128 + 4);
        float av[8] = {a0.x, a0.y, a0.z, a0.w, a1.x, a1.y, a1.z, a1.w};
        #pragma unroll
        for (int i = 0; i < 8; i++) {
            unsigned long long ap = pack2(av[i]);
            fma2(acc[i][0], ap, bq0.x);
            fma2(acc[i][1], ap, bq0.y);
            fma2(acc[i][2], ap, bq1.x);
            fma2(acc[i][3], ap, bq1.y);
        }
    }

    float hv[8][8];
    #pragma unroll
    for (int i = 0; i < 8; i++)
        #pragma unroll
        for (int jp = 0; jp < 4; jp++)
            unpack2(acc[i][jp], hv[i][2 * jp], hv[i][2 * jp + 1]);
    #pragma unroll
    for (int j = 0; j < 8; j++) {
        float bb = sb1[ty * 8 + j];
        #pragma unroll
        for (int i = 0; i < 8; i++) hv[i][j] = fmaxf(hv[i][j] + bb, 0.f);
    }

    __syncthreads();
    float* HsT = XsT;
    #pragma unroll
    for (int j = 0; j < 8; j++) {
        float4 v0 = make_float4(hv[0][j], hv[1][j], hv[2][j], hv[3][j]);
        float4 v1 = make_float4(hv[4][j], hv[5][j], hv[6][j], hv[7][j]);
        *(float4*)&HsT[(ty * 8 + j) * 128 + tx * 8]     = v0;
        *(float4*)&HsT[(ty * 8 + j) * 128 + tx * 8 + 4] = v1;
    }
    __syncthreads();

    unsigned long long a2[8][2];
    #pragma unroll
    for (int i = 0; i < 8; i++) { a2[i][0] = 0ull; a2[i][1] = 0ull; }

    const float* Ha  = HsT + tx * 8;
    const float* Wb2 = W2s + ty * 4;
    #pragma unroll 4
    for (int kk = 0; kk < 128; kk++) {
        const float* hk = Ha + kk * 128;
        float4 a0 = *(const float4*)hk;
        float4 a1 = *(const float4*)(hk + 4);
        ulonglong2 bq = *(const ulonglong2*)(Wb2 + kk * 64);
        float av[8] = {a0.x, a0.y, a0.z, a0.w, a1.x, a1.y, a1.z, a1.w};
        #pragma unroll
        for (int i = 0; i < 8; i++) {
            unsigned long long ap = pack2(av[i]);
            fma2(a2[i][0], ap, bq.x);
            fma2(a2[i][1], ap, bq.y);
        }
    }

    float4 bb2 = *(const float4*)(sb2 + ty * 4);
    #pragma unroll
    for (int i = 0; i < 8; i++) {
        float m0, m1, m2, m3;
        unpack2(a2[i][0], m0, m1);
        unpack2(a2[i][1], m2, m3);
        m0 += bb2.x; m1 += bb2.y; m2 += bb2.z; m3 += bb2.w;
        long r = r0 + tx * 8 + i;
        *(float4*)(out + r * F_ + ty * 4) = make_float4(m0, m1, m2, m3);
    }
}

// ---------------- launch ----------------
extern "C" void kernel_launch(void* const* d_in, const int* in_sizes, int n_in,
                              void* d_out, int out_size)
{
    const float* nf  = (const float*)d_in[0];
    const int*   eb  = (const int*)d_in[1];
    const int*   es  = (const int*)d_in[2];
    const int*   ed  = (const int*)d_in[3];
    const float* ev  = (const float*)d_in[4];
    const float* Wm1 = (const float*)d_in[5];
    const float* bm1 = (const float*)d_in[6];
    const float* Wm2 = (const float*)d_in[7];
    const float* bm2 = (const float*)d_in[8];
    const float* Wu1 = (const float*)d_in[9];
    const float* bu1 = (const float*)d_in[10];
    const float* Wu2 = (const float*)d_in[11];
    const float* bu2 = (const float*)d_in[12];
    float* out = (float*)d_out;

    cudaFuncSetAttribute(edge_msg_kernel, cudaFuncAttributeMaxDynamicSharedMemorySize, SMEM_BYTES);
    cudaFuncSetAttribute(node_upd_kernel, cudaFuncAttributeMaxDynamicSharedMemorySize, SMEM_BYTES);

    zero_scratch<<<2080, 256>>>();
    edge_msg_kernel<<<E_ / 128, 256, SMEM_BYTES>>>(nf, eb, es, ed, ev,
                                                   Wm1, bm1, Wm2, bm2);
    node_upd_kernel<<<ROWS_ / 128, 256, SMEM_BYTES>>>(nf, Wu1, bu1, Wu2, bu2, out);
}

// round 2
// speedup vs baseline: 6.1782x; 6.1782x over previous
#include <cuda_runtime.h>

// Problem constants
#define B_    8
#define N_    4096
#define DN_   64
#define E_    1048576
#define H_    128
#define DM_   64
#define F_    64
#define ROWS_ (B_ * N_)          // 32768

// -------- device scratch (no allocation allowed) --------
__device__ float g_P[ROWS_ * H_];     // 16 MB : nf @ Wm1[:64] + bm1
__device__ float g_Q[ROWS_ * H_];     // 16 MB : nf @ Wm1[64:]
__device__ float g_hsum[ROWS_ * H_];  // 16 MB : sum_e v * relu(P+Q)
__device__ float g_vsum[ROWS_];       // sum_e v
__device__ float g_cnts[ROWS_];       // edge counts
__device__ float g_gath[ROWS_ * DM_]; // 8 MB : finalized "gathered"

// -------- packed f32x2 helpers --------
static __device__ __forceinline__ unsigned long long pack2(float x) {
    unsigned long long r;
    asm("mov.b64 %0, {%1, %1};" : "=l"(r) : "f"(x));
    return r;
}
static __device__ __forceinline__ void fma2(unsigned long long& d,
                                            unsigned long long a,
                                            unsigned long long b) {
    asm("fma.rn.f32x2 %0, %1, %2, %0;" : "+l"(d) : "l"(a), "l"(b));
}
static __device__ __forceinline__ void unpack2(unsigned long long v, float& a, float& b) {
    asm("mov.b64 {%0, %1}, %2;" : "=f"(a), "=f"(b) : "l"(v));
}
static __device__ __forceinline__ void red4(float* p, float a, float b, float c, float d) {
    asm volatile("red.global.add.v4.f32 [%0], {%1, %2, %3, %4};"
                 :: "l"(p), "f"(a), "f"(b), "f"(c), "f"(d) : "memory");
}
static __device__ __forceinline__ void red1(float* p, float v) {
    asm volatile("red.global.add.f32 [%0], %1;" :: "l"(p), "f"(v) : "memory");
}

// ---------------- zero scratch: hsum + vsum + cnts ----------------
// float4 counts: hsum 1048576, vsum 8192, cnts 8192 -> 1064960 total
__global__ void zero_scratch() {
    unsigned i = blockIdx.x * 256u + threadIdx.x;
    float4 z = make_float4(0.f, 0.f, 0.f, 0.f);
    if (i < 1048576u)
        reinterpret_cast<float4*>(g_hsum)[i] = z;
    else if (i < 1056768u)
        reinterpret_cast<float4*>(g_vsum)[i - 1048576u] = z;
    else
        reinterpret_cast<float4*>(g_cnts)[i - 1056768u] = z;
}

// ---------------- PQ precompute: P = nf@W1a + b1, Q = nf@W1b ----------------
// block = 128 node rows, 256 threads.
#define PQ_SMEM_FLOATS (8192 + 16384 + 128)
#define PQ_SMEM_BYTES  (PQ_SMEM_FLOATS * 4)
__global__ void __launch_bounds__(256, 1)
pq_kernel(const float* __restrict__ nf, const float* __restrict__ W1,
          const float* __restrict__ b1)
{
    extern __shared__ float sm[];
    float* XsT = sm;            // [64][128]
    float* W1s = sm + 8192;     // [128][128]
    float* sb1 = sm + 24576;    // [128]

    const int tid = threadIdx.x;
    const int r0  = blockIdx.x << 7;

    if (tid < 128) sb1[tid] = b1[tid];
    {
        const float4* s1 = (const float4*)W1;
        float4*       d1 = (float4*)W1s;
        #pragma unroll 4
        for (int i = tid; i < 4096; i += 256) d1[i] = s1[i];
    }
    {
        int lane = tid & 127;
        long off = (long)(r0 + lane) * DN_;
        #pragma unroll
        for (int p = (tid >> 7); p < 16; p += 2) {
            float4 v = *(const float4*)(nf + off + p * 4);
            int k = p * 4;
            XsT[(k + 0) * 128 + lane] = v.x;
            XsT[(k + 1) * 128 + lane] = v.y;
            XsT[(k + 2) * 128 + lane] = v.z;
            XsT[(k + 3) * 128 + lane] = v.w;
        }
    }
    __syncthreads();

    const int tx = tid & 15, ty = tid >> 4;
    const float* Xa = XsT + tx * 8;

    // ---- P = X @ W1[:64] (K=64) ----
    {
        unsigned long long acc[8][4];
        #pragma unroll
        for (int i = 0; i < 8; i++)
            #pragma unroll
            for (int jp = 0; jp < 4; jp++) acc[i][jp] = 0ull;
        const float* Wb = W1s + ty * 8;
        #pragma unroll 4
        for (int kk = 0; kk < 64; kk++) {
            float4 a0 = *(const float4*)(Xa + kk * 128);
            float4 a1 = *(const float4*)(Xa + kk * 128 + 4);
            ulonglong2 bq0 = *(const ulonglong2*)(Wb + kk * 128);
            ulonglong2 bq1 = *(const ulonglong2*)(Wb + kk * 128 + 4);
            float av[8] = {a0.x, a0.y, a0.z, a0.w, a1.x, a1.y, a1.z, a1.w};
            #pragma unroll
            for (int i = 0; i < 8; i++) {
                unsigned long long ap = pack2(av[i]);
                fma2(acc[i][0], ap, bq0.x);
                fma2(acc[i][1], ap, bq0.y);
                fma2(acc[i][2], ap, bq1.x);
                fma2(acc[i][3], ap, bq1.y);
            }
        }
        float pv[8][8];
        #pragma unroll
        for (int i = 0; i < 8; i++)
            #pragma unroll
            for (int jp = 0; jp < 4; jp++)
                unpack2(acc[i][jp], pv[i][2 * jp], pv[i][2 * jp + 1]);
        #pragma unroll
        for (int j = 0; j < 8; j++) {
            float bb = sb1[ty * 8 + j];
            #pragma unroll
            for (int i = 0; i < 8; i++) pv[i][j] += bb;
        }
        #pragma unroll
        for (int i = 0; i < 8; i++) {
            float* dst = g_P + (long)(r0 + tx * 8 + i) * H_ + ty * 8;
            *(float4*)dst       = make_float4(pv[i][0], pv[i][1], pv[i][2], pv[i][3]);
            *(float4*)(dst + 4) = make_float4(pv[i][4], pv[i][5], pv[i][6], pv[i][7]);
        }
    }

    // ---- Q = X @ W1[64:] (K=64) ----
    {
        unsigned long long acc[8][4];
        #pragma unroll
        for (int i = 0; i < 8; i++)
            #pragma unroll
            for (int jp = 0; jp < 4; jp++) acc[i][jp] = 0ull;
        const float* Wb = W1s + 64 * 128 + ty * 8;
        #pragma unroll 4
        for (int kk = 0; kk < 64; kk++) {
            float4 a0 = *(const float4*)(Xa + kk * 128);
            float4 a1 = *(const float4*)(Xa + kk * 128 + 4);
            ulonglong2 bq0 = *(const ulonglong2*)(Wb + kk * 128);
            ulonglong2 bq1 = *(const ulonglong2*)(Wb + kk * 128 + 4);
            float av[8] = {a0.x, a0.y, a0.z, a0.w, a1.x, a1.y, a1.z, a1.w};
            #pragma unroll
            for (int i = 0; i < 8; i++) {
                unsigned long long ap = pack2(av[i]);
                fma2(acc[i][0], ap, bq0.x);
                fma2(acc[i][1], ap, bq0.y);
                fma2(acc[i][2], ap, bq1.x);
                fma2(acc[i][3], ap, bq1.y);
            }
        }
        float pv[8][8];
        #pragma unroll
        for (int i = 0; i < 8; i++)
            #pragma unroll
            for (int jp = 0; jp < 4; jp++)
                unpack2(acc[i][jp], pv[i][2 * jp], pv[i][2 * jp + 1]);
        #pragma unroll
        for (int i = 0; i < 8; i++) {
            float* dst = g_Q + (long)(r0 + tx * 8 + i) * H_ + ty * 8;
            *(float4*)dst       = make_float4(pv[i][0], pv[i][1], pv[i][2], pv[i][3]);
            *(float4*)(dst + 4) = make_float4(pv[i][4], pv[i][5], pv[i][6], pv[i][7]);
        }
    }
}

// ---------------- edge scatter: g_hsum[seg] += v * relu(P[src]+Q[dst]) ----------------
// One warp handles 32 consecutive edges. Lane l of iteration j reads float4 l of
// the 128-float P/Q rows of edge j (coalesced 512B), relu+scale, red4 scatter.
__global__ void __launch_bounds__(256)
edge_kernel(const int* __restrict__ eb, const int* __restrict__ es,
            const int* __restrict__ ed, const float* __restrict__ ev)
{
    const int warp = (blockIdx.x << 3) + (threadIdx.x >> 5);
    const int lane = threadIdx.x & 31;
    const int e    = (warp << 5) + lane;

    int   b   = eb[e];
    int   seg = b * N_ + es[e];
    int   qr  = b * N_ + ed[e];
    float v   = ev[e];

    red1(&g_cnts[seg], 1.0f);
    red1(&g_vsum[seg], v);

    const float4* P4 = (const float4*)g_P;
    const float4* Q4 = (const float4*)g_Q;

    #pragma unroll 4
    for (int j = 0; j < 32; j++) {
        int   sj = __shfl_sync(0xffffffffu, seg, j);
        int   qj = __shfl_sync(0xffffffffu, qr, j);
        float vj = __shfl_sync(0xffffffffu, v, j);
        float4 p = P4[sj * 32 + lane];
        float4 q = Q4[qj * 32 + lane];
        float m0 = fmaxf(p.x + q.x, 0.f) * vj;
        float m1 = fmaxf(p.y + q.y, 0.f) * vj;
        float m2 = fmaxf(p.z + q.z, 0.f) * vj;
        float m3 = fmaxf(p.w + q.w, 0.f) * vj;
        red4(g_hsum + (long)sj * H_ + lane * 4, m0, m1, m2, m3);
    }
}

// ---------------- gathered = (hsum @ W2 + b2*vsum) / max(cnt,1) ----------------
#define GATH_SMEM_FLOATS (16384 + 8192 + 64 + 128 + 128)
#define GATH_SMEM_BYTES  (GATH_SMEM_FLOATS * 4)
__global__ void __launch_bounds__(256, 1)
gath_kernel(const float* __restrict__ W2, const float* __restrict__ b2)
{
    extern __shared__ float sm[];
    float* HsT  = sm;               // [128][128]
    float* W2s  = sm + 16384;       // [128][64]
    float* sb2  = sm + 24576;       // [64]
    float* sInv = sm + 24640;       // [128]
    float* sVs  = sm + 24768;       // [128]

    const int tid = threadIdx.x;
    const int r0  = blockIdx.x << 7;

    if (tid < 64) sb2[tid] = b2[tid];
    if (tid < 128) {
        float c = g_cnts[r0 + tid];
        sInv[tid] = 1.0f / fmaxf(c, 1.0f);
        sVs[tid]  = g_vsum[r0 + tid];
    }
    {
        const float4* s2 = (const float4*)W2;
        float4*       d2 = (float4*)W2s;
        #pragma unroll 2
        for (int i = tid; i < 2048; i += 256) d2[i] = s2[i];
    }
    {
        int lane = tid & 127;
        long off = (long)(r0 + lane) * H_;
        #pragma unroll
        for (int p = (tid >> 7); p < 32; p += 2) {
            float4 v = *(const float4*)(g_hsum + off + p * 4);
            int k = p * 4;
            HsT[(k + 0) * 128 + lane] = v.x;
            HsT[(k + 1) * 128 + lane] = v.y;
            HsT[(k + 2) * 128 + lane] = v.z;
            HsT[(k + 3) * 128 + lane] = v.w;
        }
    }
    __syncthreads();

    const int tx = tid & 15, ty = tid >> 4;
    unsigned long long acc[8][2];
    #pragma unroll
    for (int i = 0; i < 8; i++) { acc[i][0] = 0ull; acc[i][1] = 0ull; }

    const float* Ha  = HsT + tx * 8;
    const float* Wb2 = W2s + ty * 4;
    #pragma unroll 4
    for (int kk = 0; kk < 128; kk++) {
        const float* hk = Ha + kk * 128;
        float4 a0 = *(const float4*)hk;
        float4 a1 = *(const float4*)(hk + 4);
        ulonglong2 bq = *(const ulonglong2*)(Wb2 + kk * 64);
        float av[8] = {a0.x, a0.y, a0.z, a0.w, a1.x, a1.y, a1.z, a1.w};
        #pragma unroll
        for (int i = 0; i < 8; i++) {
            unsigned long long ap = pack2(av[i]);
            fma2(acc[i][0], ap, bq.x);
            fma2(acc[i][1], ap, bq.y);
        }
    }

    float4 bb2 = *(const float4*)(sb2 + ty * 4);
    #pragma unroll
    for (int i = 0; i < 8; i++) {
        float m0, m1, m2, m3;
        unpack2(acc[i][0], m0, m1);
        unpack2(acc[i][1], m2, m3);
        int   rl  = tx * 8 + i;
        float inv = sInv[rl];
        float vs  = sVs[rl];
        m0 = (m0 + bb2.x * vs) * inv;
        m1 = (m1 + bb2.y * vs) * inv;
        m2 = (m2 + bb2.z * vs) * inv;
        m3 = (m3 + bb2.w * vs) * inv;
        *(float4*)(g_gath + (long)(r0 + rl) * DM_ + ty * 4) = make_float4(m0, m1, m2, m3);
    }
}

// ---------------- node update MLP ----------------
#define NODE_SMEM_FLOATS (16384 + 16384 + 8192 + 128 + 64)
#define NODE_SMEM_BYTES  (NODE_SMEM_FLOATS * 4)
__global__ void __launch_bounds__(256, 1)
node_upd_kernel(const float* __restrict__ nf,
                const float* __restrict__ W1, const float* __restrict__ b1,
                const float* __restrict__ W2, const float* __restrict__ b2,
                float* __restrict__ out)
{
    extern __shared__ float sm[];
    float* XsT = sm;                // [128][128]
    float* W1s = sm + 16384;        // [128][128]
    float* W2s = sm + 32768;        // [128][64]
    float* sb1 = sm + 40960;
    float* sb2 = sm + 41088;

    const int tid = threadIdx.x;
    const int r0  = blockIdx.x << 7;

    if (tid < 128) {
        sb1[tid] = b1[tid];
        if (tid < 64) sb2[tid] = b2[tid];
    }
    {
        const float4* s1 = (const float4*)W1;
        float4*       d1 = (float4*)W1s;
        #pragma unroll 4
        for (int i = tid; i < 4096; i += 256) d1[i] = s1[i];
        const float4* s2 = (const float4*)W2;
        float4*       d2 = (float4*)W2s;
        #pragma unroll 2
        for (int i = tid; i < 2048; i += 256) d2[i] = s2[i];
    }
    {
        int lane = tid & 127;
        int r = r0 + lane;
        #pragma unroll
        for (int p = (tid >> 7); p < 32; p += 2) {
            float4 v = (p < 16) ? *(const float4*)(nf + (long)r * DN_ + p * 4)
                                : *(const float4*)(g_gath + (long)r * DM_ + (p - 16) * 4);
            int k = p * 4;
            XsT[(k + 0) * 128 + lane] = v.x;
            XsT[(k + 1) * 128 + lane] = v.y;
            XsT[(k + 2) * 128 + lane] = v.z;
            XsT[(k + 3) * 128 + lane] = v.w;
        }
    }
    __syncthreads();

    const int tx = tid & 15, ty = tid >> 4;

    unsigned long long acc[8][4];
    #pragma unroll
    for (int i = 0; i < 8; i++)
        #pragma unroll
        for (int jp = 0; jp < 4; jp++) acc[i][jp] = 0ull;

    const float* Xa = XsT + tx * 8;
    const float* Wb = W1s + ty * 8;
    #pragma unroll 4
    for (int kk = 0; kk < 128; kk++) {
        float4 a0 = *(const float4*)(Xa + kk * 128);
        float4 a1 = *(const float4*)(Xa + kk * 128 + 4);
        ulonglong2 bq0 = *(const ulonglong2*)(Wb + kk * 128);
        ulonglong2 bq1 = *(const ulonglong2*)(Wb + kk * 128 + 4);
        float av[8] = {a0.x, a0.y, a0.z, a0.w, a1.x, a1.y, a1.z, a1.w};
        #pragma unroll
        for (int i = 0; i < 8; i++) {
            unsigned long long ap = pack2(av[i]);
            fma2(acc[i][0], ap, bq0.x);
            fma2(acc[i][1], ap, bq0.y);
            fma2(acc[i][2], ap, bq1.x);
            fma2(acc[i][3], ap, bq1.y);
        }
    }

    float hv[8][8];
    #pragma unroll
    for (int i = 0; i < 8; i++)
        #pragma unroll
        for (int jp = 0; jp < 4; jp++)
            unpack2(acc[i][jp], hv[i][2 * jp], hv[i][2 * jp + 1]);
    #pragma unroll
    for (int j = 0; j < 8; j++) {
        float bb = sb1[ty * 8 + j];
        #pragma unroll
        for (int i = 0; i < 8; i++) hv[i][j] = fmaxf(hv[i][j] + bb, 0.f);
    }

    __syncthreads();
    float* HsT = XsT;
    #pragma unroll
    for (int j = 0; j < 8; j++) {
        float4 v0 = make_float4(hv[0][j], hv[1][j], hv[2][j], hv[3][j]);
        float4 v1 = make_float4(hv[4][j], hv[5][j], hv[6][j], hv[7][j]);
        *(float4*)&HsT[(ty * 8 + j) * 128 + tx * 8]     = v0;
        *(float4*)&HsT[(ty * 8 + j) * 128 + tx * 8 + 4] = v1;
    }
    __syncthreads();

    unsigned long long a2[8][2];
    #pragma unroll
    for (int i = 0; i < 8; i++) { a2[i][0] = 0ull; a2[i][1] = 0ull; }

    const float* Ha  = HsT + tx * 8;
    const float* Wb2 = W2s + ty * 4;
    #pragma unroll 4
    for (int kk = 0; kk < 128; kk++) {
        const float* hk = Ha + kk * 128;
        float4 a0 = *(const float4*)hk;
        float4 a1 = *(const float4*)(hk + 4);
        ulonglong2 bq = *(const ulonglong2*)(Wb2 + kk * 64);
        float av[8] = {a0.x, a0.y, a0.z, a0.w, a1.x, a1.y, a1.z, a1.w};
        #pragma unroll
        for (int i = 0; i < 8; i++) {
            unsigned long long ap = pack2(av[i]);
            fma2(a2[i][0], ap, bq.x);
            fma2(a2[i][1], ap, bq.y);
        }
    }

    float4 bb2 = *(const float4*)(sb2 + ty * 4);
    #pragma unroll
    for (int i = 0; i < 8; i++) {
        float m0, m1, m2, m3;
        unpack2(a2[i][0], m0, m1);
        unpack2(a2[i][1], m2, m3);
        m0 += bb2.x; m1 += bb2.y; m2 += bb2.z; m3 += bb2.w;
        long r = r0 + tx * 8 + i;
        *(float4*)(out + r * F_ + ty * 4) = make_float4(m0, m1, m2, m3);
    }
}

// ---------------- launch ----------------
extern "C" void kernel_launch(void* const* d_in, const int* in_sizes, int n_in,
                              void* d_out, int out_size)
{
    (void)in_sizes; (void)n_in; (void)out_size;
    const float* nf  = (const float*)d_in[0];
    const int*   eb  = (const int*)d_in[1];
    const int*   es  = (const int*)d_in[2];
    const int*   ed  = (const int*)d_in[3];
    const float* ev  = (const float*)d_in[4];
    const float* Wm1 = (const float*)d_in[5];
    const float* bm1 = (const float*)d_in[6];
    const float* Wm2 = (const float*)d_in[7];
    const float* bm2 = (const float*)d_in[8];
    const float* Wu1 = (const float*)d_in[9];
    const float* bu1 = (const float*)d_in[10];
    const float* Wu2 = (const float*)d_in[11];
    const float* bu2 = (const float*)d_in[12];
    float* out = (float*)d_out;

    cudaFuncSetAttribute(pq_kernel,       cudaFuncAttributeMaxDynamicSharedMemorySize, PQ_SMEM_BYTES);
    cudaFuncSetAttribute(gath_kernel,     cudaFuncAttributeMaxDynamicSharedMemorySize, GATH_SMEM_BYTES);
    cudaFuncSetAttribute(node_upd_kernel, cudaFuncAttributeMaxDynamicSharedMemorySize, NODE_SMEM_BYTES);

    zero_scratch<<<4160, 256>>>();
    pq_kernel<<<ROWS_ / 128, 256, PQ_SMEM_BYTES>>>(nf, Wm1, bm1);
    edge_kernel<<<E_ / 256, 256>>>(eb, es, ed, ev);
    gath_kernel<<<ROWS_ / 128, 256, GATH_SMEM_BYTES>>>(Wm2, bm2);
    node_upd_kernel<<<ROWS_ / 128, 256, NODE_SMEM_BYTES>>>(nf, Wu1, bu1, Wu2, bu2, out);
}

// round 4
// speedup vs baseline: 6.1975x; 1.0031x over previous
#include <cuda_runtime.h>

// Problem constants
#define B_    8
#define N_    4096
#define DN_   64
#define E_    1048576
#define H_    128
#define DM_   64
#define F_    64
#define ROWS_ (B_ * N_)          // 32768

// -------- device scratch (no allocation allowed) --------
__device__ float g_P[ROWS_ * H_];     // 16 MB : nf @ Wm1[:64] + bm1
__device__ float g_Q[ROWS_ * H_];     // 16 MB : nf @ Wm1[64:]
__device__ float g_hsum[ROWS_ * H_];  // 16 MB : sum_e v * relu(P+Q), per segment
__device__ float g_vsumf[ROWS_];      // sum_e v per segment
__device__ float g_cntf[ROWS_];       // edge count per segment (float)
__device__ int   g_cnt[ROWS_];        // histogram
__device__ int   g_start[ROWS_];      // exclusive prefix
__device__ int   g_cur[ROWS_];        // scatter cursors
__device__ int   g_sdst[E_];          // sorted: dst row id per edge
__device__ float g_sv[E_];            // sorted: edge value
__device__ float g_Wc[H_ * 128];      // Wm2 @ Wu1b  (128x128)
__device__ float g_r[128];            // b2 @ Wu1b

// -------- packed f32x2 helpers --------
static __device__ __forceinline__ unsigned long long pack2(float x) {
    unsigned long long r;
    asm("mov.b64 %0, {%1, %1};" : "=l"(r) : "f"(x));
    return r;
}
static __device__ __forceinline__ void fma2(unsigned long long& d,
                                            unsigned long long a,
                                            unsigned long long b) {
    asm("fma.rn.f32x2 %0, %1, %2, %0;" : "+l"(d) : "l"(a), "l"(b));
}
static __device__ __forceinline__ void unpack2(unsigned long long v, float& a, float& b) {
    asm("mov.b64 {%0, %1}, %2;" : "=f"(a), "=f"(b) : "l"(v));
}

// ---------------- zero histogram (128 KB only) ----------------
__global__ void zero_hist() {
    unsigned i = blockIdx.x * 256u + threadIdx.x;
    reinterpret_cast<int4*>(g_cnt)[i] = make_int4(0, 0, 0, 0);
}

// ---------------- histogram over segments ----------------
__global__ void __launch_bounds__(256)
hist_kernel(const int* __restrict__ eb, const int* __restrict__ es)
{
    int e = blockIdx.x * 256 + threadIdx.x;
    int seg = eb[e] * N_ + es[e];
    atomicAdd(&g_cnt[seg], 1);
}

// ---------------- exclusive scan (single block, 1024 threads) ----------------
__global__ void __launch_bounds__(1024)
scan_kernel()
{
    __shared__ int sps[1024];
    int tid  = threadIdx.x;
    int base = tid * 32;
    int loc[32];
    int s = 0;
    #pragma unroll
    for (int j = 0; j < 32; j++) { loc[j] = g_cnt[base + j]; s += loc[j]; }
    sps[tid] = s;
    __syncthreads();
    // Hillis-Steele inclusive scan over 1024 partials
    for (int off = 1; off < 1024; off <<= 1) {
        int v = sps[tid];
        int u = (tid >= off) ? sps[tid - off] : 0;
        __syncthreads();
        sps[tid] = v + u;
        __syncthreads();
    }
    int excl = (tid == 0) ? 0 : sps[tid - 1];
    #pragma unroll
    for (int j = 0; j < 32; j++) {
        g_start[base + j] = excl;
        g_cur[base + j]   = excl;
        excl += loc[j];
    }
}

// ---------------- scatter edges into buckets ----------------
__global__ void __launch_bounds__(256)
scatter_kernel(const int* __restrict__ eb, const int* __restrict__ es,
               const int* __restrict__ ed, const float* __restrict__ ev)
{
    int e = blockIdx.x * 256 + threadIdx.x;
    int b   = eb[e];
    int seg = b * N_ + es[e];
    int pos = atomicAdd(&g_cur[seg], 1);
    g_sdst[pos] = b * N_ + ed[e];
    g_sv[pos]   = ev[e];
}

// ---------------- PQ precompute: P = nf@W1a + b1, Q = nf@W1b ----------------
#define PQ_SMEM_FLOATS (8192 + 16384 + 128)
#define PQ_SMEM_BYTES  (PQ_SMEM_FLOATS * 4)
__global__ void __launch_bounds__(256, 1)
pq_kernel(const float* __restrict__ nf, const float* __restrict__ W1,
          const float* __restrict__ b1)
{
    extern __shared__ float sm[];
    float* XsT = sm;            // [64][128]
    float* W1s = sm + 8192;     // [128][128]
    float* sb1 = sm + 24576;    // [128]

    const int tid = threadIdx.x;
    const int r0  = blockIdx.x << 7;

    if (tid < 128) sb1[tid] = b1[tid];
    {
        const float4* s1 = (const float4*)W1;
        float4*       d1 = (float4*)W1s;
        #pragma unroll 4
        for (int i = tid; i < 4096; i += 256) d1[i] = s1[i];
    }
    {
        int lane = tid & 127;
        long off = (long)(r0 + lane) * DN_;
        #pragma unroll
        for (int p = (tid >> 7); p < 16; p += 2) {
            float4 v = *(const float4*)(nf + off + p * 4);
            int k = p * 4;
            XsT[(k + 0) * 128 + lane] = v.x;
            XsT[(k + 1) * 128 + lane] = v.y;
            XsT[(k + 2) * 128 + lane] = v.z;
            XsT[(k + 3) * 128 + lane] = v.w;
        }
    }
    __syncthreads();

    const int tx = tid & 15, ty = tid >> 4;
    const float* Xa = XsT + tx * 8;

    #pragma unroll
    for (int half = 0; half < 2; half++) {
        unsigned long long acc[8][4];
        #pragma unroll
        for (int i = 0; i < 8; i++)
            #pragma unroll
            for (int jp = 0; jp < 4; jp++) acc[i][jp] = 0ull;
        const float* Wb = W1s + half * 64 * 128 + ty * 8;
        #pragma unroll 4
        for (int kk = 0; kk < 64; kk++) {
            float4 a0 = *(const float4*)(Xa + kk * 128);
            float4 a1 = *(const float4*)(Xa + kk * 128 + 4);
            ulonglong2 bq0 = *(const ulonglong2*)(Wb + kk * 128);
            ulonglong2 bq1 = *(const ulonglong2*)(Wb + kk * 128 + 4);
            float av[8] = {a0.x, a0.y, a0.z, a0.w, a1.x, a1.y, a1.z, a1.w};
            #pragma unroll
            for (int i = 0; i < 8; i++) {
                unsigned long long ap = pack2(av[i]);
                fma2(acc[i][0], ap, bq0.x);
                fma2(acc[i][1], ap, bq0.y);
                fma2(acc[i][2], ap, bq1.x);
                fma2(acc[i][3], ap, bq1.y);
            }
        }
        float pv[8][8];
        #pragma unroll
        for (int i = 0; i < 8; i++)
            #pragma unroll
            for (int jp = 0; jp < 4; jp++)
                unpack2(acc[i][jp], pv[i][2 * jp], pv[i][2 * jp + 1]);
        if (half == 0) {
            #pragma unroll
            for (int j = 0; j < 8; j++) {
                float bb = sb1[ty * 8 + j];
                #pragma unroll
                for (int i = 0; i < 8; i++) pv[i][j] += bb;
            }
        }
        float* G = (half == 0) ? g_P : g_Q;
        #pragma unroll
        for (int i = 0; i < 8; i++) {
            float* dst = G + (long)(r0 + tx * 8 + i) * H_ + ty * 8;
            *(float4*)dst       = make_float4(pv[i][0], pv[i][1], pv[i][2], pv[i][3]);
            *(float4*)(dst + 4) = make_float4(pv[i][4], pv[i][5], pv[i][6], pv[i][7]);
        }
    }
}

// ---------------- Wc = Wm2 @ Wu1b, r = b2 @ Wu1b ----------------
// Block computes 16 h-rows of Wc; stages only those 16 rows of Wm2 (4 KB)
// plus the full Wu1b (32 KB) -> 36 KB static smem (under the 48 KB cap).
__global__ void __launch_bounds__(256)
wc_kernel(const float* __restrict__ Wm2, const float* __restrict__ b2,
          const float* __restrict__ Wu1)
{
    __shared__ float sW2[16 * DM_];   // this block's 16 h-rows: [16][64]
    __shared__ float sU[DM_ * 128];   // Wu1b [d][u] 64x128
    int tid = threadIdx.x;
    int h0  = blockIdx.x * 16;
    {
        const float4* s = (const float4*)(Wm2 + h0 * DM_);
        if (tid < 256) {
            ((float4*)sW2)[tid] = s[tid];                   // 256 float4 = 16*64
        }
        const float4* u = (const float4*)(Wu1 + DN_ * 128);
        #pragma unroll 2
        for (int i = tid; i < 2048; i += 256) ((float4*)sU)[i] = u[i];
    }
    __syncthreads();

    int hl = tid >> 4;                 // 0..15 local h row
    int u0 = (tid & 15) * 8;
    float acc[8] = {0, 0, 0, 0, 0, 0, 0, 0};
    #pragma unroll 4
    for (int d = 0; d < 64; d++) {
        float a = sW2[hl * 64 + d];
        const float* uu = sU + d * 128 + u0;
        #pragma unroll
        for (int j = 0; j < 8; j++) acc[j] += a * uu[j];
    }
    #pragma unroll
    for (int j = 0; j < 8; j++) g_Wc[(h0 + hl) * 128 + u0 + j] = acc[j];

    if (blockIdx.x == 0 && tid < 128) {
        float rr = 0.f;
        #pragma unroll 4
        for (int d = 0; d < 64; d++) rr += b2[d] * sU[d * 128 + tid];
        g_r[tid] = rr;
    }
}

// ---------------- per-segment accumulation (no atomics) ----------------
// One warp per segment. Lane l owns float4 l of the 128-float rows.
__global__ void __launch_bounds__(256)
segacc_kernel()
{
    const int seg  = (blockIdx.x << 3) + (threadIdx.x >> 5);
    const int lane = threadIdx.x & 31;

    const int start = g_start[seg];
    const int cnt   = g_cnt[seg];

    const float4* P4 = (const float4*)g_P;
    const float4* Q4 = (const float4*)g_Q;

    float4 p = P4[seg * 32 + lane];
    float4 acc = make_float4(0.f, 0.f, 0.f, 0.f);
    float  vs  = 0.f;

    int i = 0;
    for (; i + 4 <= cnt; i += 4) {
        int   d0 = g_sdst[start + i + 0], d1 = g_sdst[start + i + 1];
        int   d2 = g_sdst[start + i + 2], d3 = g_sdst[start + i + 3];
        float v0 = g_sv[start + i + 0],   v1 = g_sv[start + i + 1];
        float v2 = g_sv[start + i + 2],   v3 = g_sv[start + i + 3];
        float4 q0 = Q4[d0 * 32 + lane];
        float4 q1 = Q4[d1 * 32 + lane];
        float4 q2 = Q4[d2 * 32 + lane];
        float4 q3 = Q4[d3 * 32 + lane];
        acc.x += v0 * fmaxf(p.x + q0.x, 0.f); acc.y += v0 * fmaxf(p.y + q0.y, 0.f);
        acc.z += v0 * fmaxf(p.z + q0.z, 0.f); acc.w += v0 * fmaxf(p.w + q0.w, 0.f);
        acc.x += v1 * fmaxf(p.x + q1.x, 0.f); acc.y += v1 * fmaxf(p.y + q1.y, 0.f);
        acc.z += v1 * fmaxf(p.z + q1.z, 0.f); acc.w += v1 * fmaxf(p.w + q1.w, 0.f);
        acc.x += v2 * fmaxf(p.x + q2.x, 0.f); acc.y += v2 * fmaxf(p.y + q2.y, 0.f);
        acc.z += v2 * fmaxf(p.z + q2.z, 0.f); acc.w += v2 * fmaxf(p.w + q2.w, 0.f);
        acc.x += v3 * fmaxf(p.x + q3.x, 0.f); acc.y += v3 * fmaxf(p.y + q3.y, 0.f);
        acc.z += v3 * fmaxf(p.z + q3.z, 0.f); acc.w += v3 * fmaxf(p.w + q3.w, 0.f);
        vs += v0 + v1 + v2 + v3;
    }
    for (; i < cnt; i++) {
        int   d = g_sdst[start + i];
        float v = g_sv[start + i];
        float4 q = Q4[d * 32 + lane];
        acc.x += v * fmaxf(p.x + q.x, 0.f);
        acc.y += v * fmaxf(p.y + q.y, 0.f);
        acc.z += v * fmaxf(p.z + q.z, 0.f);
        acc.w += v * fmaxf(p.w + q.w, 0.f);
        vs += v;
    }

    ((float4*)g_hsum)[seg * 32 + lane] = acc;
    if (lane == 0) {
        g_vsumf[seg] = vs;
        g_cntf[seg]  = (float)cnt;
    }
}

// ---------------- fused node update ----------------
// hidden = relu( nf@Wu1a + (inv*hsum)@Wc + (inv*vsum)*r + bu1 ); out = hidden@Wu2 + bu2
// smem: XsT[192][128] | W1s[192][128] | sb1[128] sb2[64] sVr[128] sr[128]
#define NODE_SMEM_FLOATS (24576 + 24576 + 128 + 64 + 128 + 128)
#define NODE_SMEM_BYTES  (NODE_SMEM_FLOATS * 4)
__global__ void __launch_bounds__(256, 1)
node_upd_kernel(const float* __restrict__ nf,
                const float* __restrict__ Wu1, const float* __restrict__ bu1,
                const float* __restrict__ Wu2, const float* __restrict__ bu2,
                float* __restrict__ out)
{
    extern __shared__ float sm[];
    float* XsT = sm;                  // [192][128]
    float* W1s = sm + 24576;          // [192][128] : rows 0..63 Wu1a, 64..191 Wc
    float* sb1 = sm + 49152;          // [128]
    float* sb2 = sm + 49280;          // [64]
    float* sVr = sm + 49344;          // [128] vsum*inv per row
    float* sr  = sm + 49472;          // [128] r

    const int tid = threadIdx.x;
    const int r0  = blockIdx.x << 7;

    if (tid < 128) {
        sb1[tid] = bu1[tid];
        sr[tid]  = g_r[tid];
        if (tid < 64) sb2[tid] = bu2[tid];
    }
    {
        const float4* sa = (const float4*)Wu1;        // first 64 rows
        float4*       da = (float4*)W1s;
        #pragma unroll 2
        for (int i = tid; i < 2048; i += 256) da[i] = sa[i];
        const float4* sc = (const float4*)g_Wc;
        float4*       dc = (float4*)(W1s + 64 * 128);
        #pragma unroll 4
        for (int i = tid; i < 4096; i += 256) dc[i] = sc[i];
    }
    {
        int lane = tid & 127;
        int r = r0 + lane;
        float c   = g_cntf[r];
        float inv = 1.0f / fmaxf(c, 1.0f);
        if ((tid >> 7) == 0) sVr[lane] = g_vsumf[r] * inv;
        #pragma unroll
        for (int p = (tid >> 7); p < 48; p += 2) {
            float4 v;
            int k;
            if (p < 16) {
                v = *(const float4*)(nf + (long)r * DN_ + p * 4);
                k = p * 4;
            } else {
                v = *(const float4*)(g_hsum + (long)r * H_ + (p - 16) * 4);
                v.x *= inv; v.y *= inv; v.z *= inv; v.w *= inv;
                k = 64 + (p - 16) * 4;
            }
            XsT[(k + 0) * 128 + lane] = v.x;
            XsT[(k + 1) * 128 + lane] = v.y;
            XsT[(k + 2) * 128 + lane] = v.z;
            XsT[(k + 3) * 128 + lane] = v.w;
        }
    }
    __syncthreads();

    const int tx = tid & 15, ty = tid >> 4;

    unsigned long long acc[8][4];
    #pragma unroll
    for (int i = 0; i < 8; i++)
        #pragma unroll
        for (int jp = 0; jp < 4; jp++) acc[i][jp] = 0ull;

    const float* Xa = XsT + tx * 8;
    const float* Wb = W1s + ty * 8;
    #pragma unroll 4
    for (int kk = 0; kk < 192; kk++) {
        float4 a0 = *(const float4*)(Xa + kk * 128);
        float4 a1 = *(const float4*)(Xa + kk * 128 + 4);
        ulonglong2 bq0 = *(const ulonglong2*)(Wb + kk * 128);
        ulonglong2 bq1 = *(const ulonglong2*)(Wb + kk * 128 + 4);
        float av[8] = {a0.x, a0.y, a0.z, a0.w, a1.x, a1.y, a1.z, a1.w};
        #pragma unroll
        for (int i = 0; i < 8; i++) {
            unsigned long long ap = pack2(av[i]);
            fma2(acc[i][0], ap, bq0.x);
            fma2(acc[i][1], ap, bq0.y);
            fma2(acc[i][2], ap, bq1.x);
            fma2(acc[i][3], ap, bq1.y);
        }
    }

    float hv[8][8];
    #pragma unroll
    for (int i = 0; i < 8; i++)
        #pragma unroll
        for (int jp = 0; jp < 4; jp++)
            unpack2(acc[i][jp], hv[i][2 * jp], hv[i][2 * jp + 1]);
    #pragma unroll
    for (int j = 0; j < 8; j++) {
        float bb = sb1[ty * 8 + j];
        float rr = sr[ty * 8 + j];
        #pragma unroll
        for (int i = 0; i < 8; i++)
            hv[i][j] = fmaxf(hv[i][j] + bb + sVr[tx * 8 + i] * rr, 0.f);
    }

    __syncthreads();                  // XsT + W1s reads complete
    float* HsT = sm;                  // [128][128] over XsT rows 0..127
    float* W2s = sm + 16384;          // [128][64]  over XsT rows 128..191
    #pragma unroll
    for (int j = 0; j < 8; j++) {
        float4 v0 = make_float4(hv[0][j], hv[1][j], hv[2][j], hv[3][j]);
        float4 v1 = make_float4(hv[4][j], hv[5][j], hv[6][j], hv[7][j]);
        *(float4*)&HsT[(ty * 8 + j) * 128 + tx * 8]     = v0;
        *(float4*)&HsT[(ty * 8 + j) * 128 + tx * 8 + 4] = v1;
    }
    {
        const float4* s2 = (const float4*)Wu2;
        float4*       d2 = (float4*)W2s;
        #pragma unroll 2
        for (int i = tid; i < 2048; i += 256) d2[i] = s2[i];
    }
    __syncthreads();

    unsigned long long a2[8][2];
    #pragma unroll
    for (int i = 0; i < 8; i++) { a2[i][0] = 0ull; a2[i][1] = 0ull; }

    const float* Ha  = HsT + tx * 8;
    const float* Wb2 = W2s + ty * 4;
    #pragma unroll 4
    for (int kk = 0; kk < 128; kk++) {
        const float* hk = Ha + kk * 128;
        float4 a0 = *(const float4*)hk;
        float4 a1 = *(const float4*)(hk + 4);
        ulonglong2 bq = *(const ulonglong2*)(Wb2 + kk * 64);
        float av[8] = {a0.x, a0.y, a0.z, a0.w, a1.x, a1.y, a1.z, a1.w};
        #pragma unroll
        for (int i = 0; i < 8; i++) {
            unsigned long long ap = pack2(av[i]);
            fma2(a2[i][0], ap, bq.x);
            fma2(a2[i][1], ap, bq.y);
        }
    }

    float4 bb2 = *(const float4*)(sb2 + ty * 4);
    #pragma unroll
    for (int i = 0; i < 8; i++) {
        float m0, m1, m2, m3;
        unpack2(a2[i][0], m0, m1);
        unpack2(a2[i][1], m2, m3);
        m0 += bb2.x; m1 += bb2.y; m2 += bb2.z; m3 += bb2.w;
        long r = r0 + tx * 8 + i;
        *(float4*)(out + r * F_ + ty * 4) = make_float4(m0, m1, m2, m3);
    }
}

// ---------------- launch ----------------
extern "C" void kernel_launch(void* const* d_in, const int* in_sizes, int n_in,
                              void* d_out, int out_size)
{
    (void)in_sizes; (void)n_in; (void)out_size;
    const float* nf  = (const float*)d_in[0];
    const int*   eb  = (const int*)d_in[1];
    const int*   es  = (const int*)d_in[2];
    const int*   ed  = (const int*)d_in[3];
    const float* ev  = (const float*)d_in[4];
    const float* Wm1 = (const float*)d_in[5];
    const float* bm1 = (const float*)d_in[6];
    const float* Wm2 = (const float*)d_in[7];
    const float* bm2 = (const float*)d_in[8];
    const float* Wu1 = (const float*)d_in[9];
    const float* bu1 = (const float*)d_in[10];
    const float* Wu2 = (const float*)d_in[11];
    const float* bu2 = (const float*)d_in[12];
    float* out = (float*)d_out;

    cudaFuncSetAttribute(pq_kernel,       cudaFuncAttributeMaxDynamicSharedMemorySize, PQ_SMEM_BYTES);
    cudaFuncSetAttribute(node_upd_kernel, cudaFuncAttributeMaxDynamicSharedMemorySize, NODE_SMEM_BYTES);

    zero_hist<<<32, 256>>>();                                 // 32768 ints / int4
    hist_kernel<<<E_ / 256, 256>>>(eb, es);
    scan_kernel<<<1, 1024>>>();
    scatter_kernel<<<E_ / 256, 256>>>(eb, es, ed, ev);
    pq_kernel<<<ROWS_ / 128, 256, PQ_SMEM_BYTES>>>(nf, Wm1, bm1);
    wc_kernel<<<8, 256>>>(Wm2, bm2, Wu1);
    segacc_kernel<<<ROWS_ / 8, 256>>>();
    node_upd_kernel<<<ROWS_ / 128, 256, NODE_SMEM_BYTES>>>(nf, Wu1, bu1, Wu2, bu2, out);
}